// round 17
// baseline (speedup 1.0000x reference)
#include <cuda_runtime.h>
#include <cuda_fp16.h>
#include <math.h>

#define NNODES 50000
#define NPAD   50048   // padded row count (= NTILES*64)
#define NEDGES 800000
#define NTILES 782

// ---------------- device scratch (no allocations allowed) ----------------
__device__ int     g_deg[NNODES];
__device__ int     g_rowptr[NNODES + 1];
__device__ int     g_wr[NNODES];
__device__ int     g_srcs[NEDGES];
__device__ int     g_tilectr[2];        // persistent-gemm tile counters
__device__ __half  g_feat16[NPAD * 128];// in_feat converted to fp16 (pad rows stay 0)
__device__ __half2 g_hfh[NNODES * 64];  // transformed features, fp16 [N][128]
__device__ __half  g_h1h[NPAD * 128];   // layer-1 output (relu), fp16
__device__ float   g_el[NNODES * 4];
__device__ float   g_er[NNODES * 4];
__device__ __half  g_wt1[128 * 128];    // W1 transposed [n][k] fp16
__device__ __half  g_wt2[128 * 128];    // W2 transposed [n][k] fp16

// ------- fused init: feat->fp16, convert W1/W2, zero deg, zero counters -----
#define FEAT4 (NNODES * 32)             // 1,600,000 float4 groups
__global__ void k_init(const float* __restrict__ in_feat,
                       const float* __restrict__ W1, const float* __restrict__ W2) {
    int i = blockIdx.x * blockDim.x + threadIdx.x;
    if (i < FEAT4) {
        float4 f = __ldg((const float4*)in_feat + i);
        __half2 h0 = __floats2half2_rn(f.x, f.y);
        __half2 h1 = __floats2half2_rn(f.z, f.w);
        uint2 pk;
        pk.x = *(unsigned*)&h0;
        pk.y = *(unsigned*)&h1;
        ((uint2*)g_feat16)[i] = pk;
    } else {
        int j = i - FEAT4;
        if (j < 16384) {
            int k = j >> 7, n = j & 127;
            g_wt1[n * 128 + k] = __float2half_rn(W1[k * 128 + n]);
        } else if (j < 32768) {
            int m = j - 16384;
            int k = m >> 7, n = m & 127;
            g_wt2[n * 128 + k] = __float2half_rn(W2[k * 128 + n]);
        } else if (j < 32768 + NNODES) {
            g_deg[j - 32768] = 0;
        } else if (j < 32768 + NNODES + 2) {
            g_tilectr[j - 32768 - NNODES] = 0;
        }
    }
}

// scalar, one edge per thread (4-per-thread atomics regressed in R14)
__global__ void k_hist(const int* __restrict__ dst) {
    int i = blockIdx.x * blockDim.x + threadIdx.x;
    if (i < NEDGES) atomicAdd(&g_deg[dst[i]], 1);
}

// single-block exclusive scan, smem-staged with coalesced global access
__global__ void k_scan() {
    extern __shared__ int sd[];          // NNODES ints
    __shared__ int ssum[1024];
    int tid = threadIdx.x;

    for (int i = tid; i < NNODES; i += 1024) sd[i] = g_deg[i];
    __syncthreads();

    const int CH = (NNODES + 1023) / 1024;   // 49
    int base = tid * CH;
    int local = 0;
    #pragma unroll 7
    for (int i = 0; i < CH; i++) {
        int idx = base + i;
        if (idx < NNODES) local += sd[idx];
    }
    ssum[tid] = local;
    __syncthreads();
    for (int off = 1; off < 1024; off <<= 1) {
        int v = (tid >= off) ? ssum[tid - off] : 0;
        __syncthreads();
        ssum[tid] += v;
        __syncthreads();
    }
    int run = ssum[tid] - local;
    #pragma unroll 7
    for (int i = 0; i < CH; i++) {
        int idx = base + i;
        if (idx < NNODES) {
            int d = sd[idx];
            sd[idx] = run;
            run += d;
        }
    }
    __syncthreads();
    for (int i = tid; i < NNODES; i += 1024) {
        int v = sd[i];
        g_rowptr[i] = v;
        g_wr[i] = v;
    }
    if (tid == 1023) g_rowptr[NNODES] = ssum[1023];
}

__global__ void k_fill(const int* __restrict__ src, const int* __restrict__ dst) {
    int i = blockIdx.x * blockDim.x + threadIdx.x;
    if (i < NEDGES) {
        int d = dst[i];
        int p = atomicAdd(&g_wr[d], 1);
        g_srcs[p] = src[i];
    }
}

// ---------------- persistent GEMM, cp.async double-buffered A ---------------
#define SA_STRIDE 136
#define SB_STRIDE 136
#define SA_BYTES  (64 * SA_STRIDE * 2)                        // 17408
#define GEMM_SMEM (2 * SA_BYTES + 128 * SB_STRIDE * 2)        // 69632 bytes

__device__ __forceinline__ void mma16816(float* c, unsigned a0, unsigned a1,
                                         unsigned a2, unsigned a3,
                                         unsigned b0, unsigned b1) {
    asm volatile(
        "mma.sync.aligned.m16n8k16.row.col.f32.f16.f16.f32 "
        "{%0,%1,%2,%3}, {%4,%5,%6,%7}, {%8,%9}, {%0,%1,%2,%3};"
        : "+f"(c[0]), "+f"(c[1]), "+f"(c[2]), "+f"(c[3])
        : "r"(a0), "r"(a1), "r"(a2), "r"(a3), "r"(b0), "r"(b1));
}

__device__ __forceinline__ void ldsm_x4(unsigned& r0, unsigned& r1,
                                        unsigned& r2, unsigned& r3, unsigned addr) {
    asm volatile("ldmatrix.sync.aligned.m8n8.x4.shared.b16 {%0,%1,%2,%3}, [%4];"
                 : "=r"(r0), "=r"(r1), "=r"(r2), "=r"(r3) : "r"(addr));
}

__device__ __forceinline__ void cp16(unsigned smem_addr, const void* gptr) {
    asm volatile("cp.async.cg.shared.global [%0], [%1], 16;"
                 :: "r"(smem_addr), "l"(gptr));
}
__device__ __forceinline__ void cp_commit() {
    asm volatile("cp.async.commit_group;");
}
__device__ __forceinline__ void cp_wait0() {
    asm volatile("cp.async.wait_group 0;");
}
__device__ __forceinline__ void cp_wait1() {
    asm volatile("cp.async.wait_group 1;");
}

// issue the 4 cp.asyncs for this thread's share of a 64x128 fp16 A tile
__device__ __forceinline__ void issue_A(unsigned sA_u32, const __half* feat,
                                        int row0, int tid) {
    #pragma unroll
    for (int u = 0; u < 4; u++) {
        int i = tid + u * 256;           // 0..1023
        int r = i >> 4, c = i & 15;
        cp16(sA_u32 + (r * SA_STRIDE + c * 8) * 2,
             (const void*)(feat + (row0 + r) * 128 + c * 8));
    }
    cp_commit();
}

__global__ void __launch_bounds__(256) k_gemm(const __half* __restrict__ feat,
                                              const __half* __restrict__ wt,
                                              const float* __restrict__ al,
                                              const float* __restrict__ ar,
                                              int* __restrict__ ctr) {
    extern __shared__ __half sh[];
    __half* sA0 = sh;                              // 64 x 136
    __half* sA1 = sh + 64 * SA_STRIDE;             // 64 x 136
    __half* sBt = sh + 2 * 64 * SA_STRIDE;         // 128 x 136
    __shared__ int s_tile;
    int tid = threadIdx.x;

    int warp = tid >> 5, lane = tid & 31;
    int wm = warp >> 1, wn = warp & 1;
    int g = lane >> 2, t2 = (lane & 3) * 2;
    int mbase = wm * 16;
    int nbase = wn * 64;

    unsigned sA_u32[2];
    sA_u32[0] = (unsigned)__cvta_generic_to_shared(sA0);
    sA_u32[1] = (unsigned)__cvta_generic_to_shared(sA1);
    unsigned sB_u32 = (unsigned)__cvta_generic_to_shared(sBt);

    unsigned a_frag_off = ((mbase + (lane & 15)) * SA_STRIDE + (lane >> 4) * 8) * 2;
    int nrow_off = (lane & 7) + ((lane >> 4) & 1) * 8;
    int kcol_off = ((lane >> 3) & 1) * 8;
    unsigned b_addr = sB_u32 + ((nbase + nrow_off) * SB_STRIDE + kcol_off) * 2;
    const unsigned PSTRIDE = 16 * SB_STRIDE * 2;

    // fill sBt once per CTA (coalesced uint4 copy)
    const uint4* Wt4 = (const uint4*)wt;
    #pragma unroll 8
    for (int i = tid; i < 2048; i += 256) {
        int n = i >> 4, c = i & 15;
        *(uint4*)&sBt[n * SB_STRIDE + c * 8] = Wt4[i];
    }

    // prologue: steal first tile, prefetch its A
    if (tid == 0) s_tile = atomicAdd(ctr, 1);
    __syncthreads();
    int tile = s_tile;
    int cur = 0;
    if (tile < NTILES) issue_A(sA_u32[0], feat, tile * 64, tid);

    while (tile < NTILES) {
        // steal next; the syncthreads also guarantees all warps finished
        // reading buf[cur^1] (last iteration's buffer) before refill below
        if (tid == 0) s_tile = atomicAdd(ctr, 1);
        __syncthreads();
        int next = s_tile;
        if (next < NTILES) {
            issue_A(sA_u32[cur ^ 1], feat, next * 64, tid);
            cp_wait1();          // buf[cur] complete (next's group still inflight)
        } else {
            cp_wait0();
        }
        __syncthreads();         // buf[cur] visible to all warps

        int row0 = tile * 64;
        unsigned a_addr = sA_u32[cur] + a_frag_off;

        float acc[8][4];
        #pragma unroll
        for (int j = 0; j < 8; j++) {
            acc[j][0] = acc[j][1] = acc[j][2] = acc[j][3] = 0.f;
        }

        #pragma unroll
        for (int ks = 0; ks < 8; ks++) {
            unsigned a0, a1, a2, a3;
            ldsm_x4(a0, a1, a2, a3, a_addr + ks * 32);
            #pragma unroll
            for (int p = 0; p < 4; p++) {
                unsigned b0, b1, b2, b3;
                ldsm_x4(b0, b1, b2, b3, b_addr + p * PSTRIDE + ks * 32);
                mma16816(acc[2 * p],     a0, a1, a2, a3, b0, b1);
                mma16816(acc[2 * p + 1], a0, a1, a2, a3, b2, b3);
            }
        }

        // epilogue (overlaps next tile's inflight cp.async)
        int r0 = row0 + mbase + g;
        int r1 = r0 + 8;
        __half* hf = (__half*)g_hfh;
        float el0a = 0.f, er0a = 0.f, el1a = 0.f, er1a = 0.f;
        float el0b = 0.f, er0b = 0.f, el1b = 0.f, er1b = 0.f;
        #pragma unroll
        for (int j = 0; j < 8; j++) {
            int n = nbase + j * 8 + t2;
            if (r0 < NNODES)
                *(__half2*)&hf[r0 * 128 + n] = __floats2half2_rn(acc[j][0], acc[j][1]);
            if (r1 < NNODES)
                *(__half2*)&hf[r1 * 128 + n] = __floats2half2_rn(acc[j][2], acc[j][3]);
            float av0 = __ldg(&al[n]), av1 = __ldg(&al[n + 1]);
            float rv0 = __ldg(&ar[n]), rv1 = __ldg(&ar[n + 1]);
            float pe0 = acc[j][0] * av0 + acc[j][1] * av1;
            float pr0 = acc[j][0] * rv0 + acc[j][1] * rv1;
            float pe1 = acc[j][2] * av0 + acc[j][3] * av1;
            float pr1 = acc[j][2] * rv0 + acc[j][3] * rv1;
            if (j < 4) { el0a += pe0; er0a += pr0; el1a += pe1; er1a += pr1; }
            else       { el0b += pe0; er0b += pr0; el1b += pe1; er1b += pr1; }
        }
        #pragma unroll
        for (int off = 1; off <= 2; off <<= 1) {
            el0a += __shfl_xor_sync(0xffffffffu, el0a, off);
            er0a += __shfl_xor_sync(0xffffffffu, er0a, off);
            el1a += __shfl_xor_sync(0xffffffffu, el1a, off);
            er1a += __shfl_xor_sync(0xffffffffu, er1a, off);
            el0b += __shfl_xor_sync(0xffffffffu, el0b, off);
            er0b += __shfl_xor_sync(0xffffffffu, er0b, off);
            el1b += __shfl_xor_sync(0xffffffffu, el1b, off);
            er1b += __shfl_xor_sync(0xffffffffu, er1b, off);
        }
        if ((lane & 3) == 0) {
            int h0 = wn * 2;
            if (r0 < NNODES) {
                g_el[r0 * 4 + h0]     = el0a;  g_er[r0 * 4 + h0]     = er0a;
                g_el[r0 * 4 + h0 + 1] = el0b;  g_er[r0 * 4 + h0 + 1] = er0b;
            }
            if (r1 < NNODES) {
                g_el[r1 * 4 + h0]     = el1a;  g_er[r1 * 4 + h0]     = er1a;
                g_el[r1 * 4 + h0 + 1] = el1b;  g_er[r1 * 4 + h0 + 1] = er1b;
            }
        }

        tile = next;
        cur ^= 1;
    }
}

// ---------------- warp-per-dst aggregation (R5 version — best) ----------------
__device__ __forceinline__ float lrelu(float x) { return x > 0.f ? x : 0.2f * x; }

template <bool FINAL>
__global__ void __launch_bounds__(256) k_agg(const float* __restrict__ bias,
                                             const float* __restrict__ Wout,
                                             const float* __restrict__ bout,
                                             float* __restrict__ outp) {
    int gw = (blockIdx.x * blockDim.x + threadIdx.x) >> 5;
    int lane = threadIdx.x & 31;
    if (gw >= NNODES) return;
    int n = gw;
    int start = g_rowptr[n], end = g_rowptr[n + 1];
    int h = lane >> 3;
    float er_h = __ldg(&g_er[n * 4 + h]);

    float den = 0.f;
    float4 acc = make_float4(0.f, 0.f, 0.f, 0.f);
    #pragma unroll 4
    for (int j = start; j < end; j++) {
        int s = __ldg(&g_srcs[j]);
        float el = __ldg(&g_el[s * 4 + h]);
        float x = __expf(lrelu(el + er_h));
        den += x;
        uint2 pk = __ldg((const uint2*)(g_hfh + s * 64) + lane);
        float2 v0 = __half22float2(*(__half2*)&pk.x);
        float2 v1 = __half22float2(*(__half2*)&pk.y);
        acc.x += v0.x * x; acc.y += v0.y * x;
        acc.z += v1.x * x; acc.w += v1.y * x;
    }

    float inv = 1.0f / fmaxf(den, 1e-30f);
    float4 b4 = ((const float4*)bias)[lane];
    float4 val;
    val.x = acc.x * inv + b4.x;
    val.y = acc.y * inv + b4.y;
    val.z = acc.z * inv + b4.z;
    val.w = acc.w * inv + b4.w;

    if (!FINAL) {
        val.x = fmaxf(val.x, 0.f); val.y = fmaxf(val.y, 0.f);
        val.z = fmaxf(val.z, 0.f); val.w = fmaxf(val.w, 0.f);
        uint2 pk;
        __half2 h0 = __floats2half2_rn(val.x, val.y);
        __half2 h1 = __floats2half2_rn(val.z, val.w);
        pk.x = *(unsigned*)&h0;
        pk.y = *(unsigned*)&h1;
        ((uint2*)g_h1h)[n * 32 + lane] = pk;
    } else {
        #pragma unroll
        for (int off = 8; off <= 16; off <<= 1) {
            val.x += __shfl_xor_sync(0xffffffffu, val.x, off);
            val.y += __shfl_xor_sync(0xffffffffu, val.y, off);
            val.z += __shfl_xor_sync(0xffffffffu, val.z, off);
            val.w += __shfl_xor_sync(0xffffffffu, val.w, off);
        }
        val.x = fmaxf(val.x * 0.25f, 0.f);
        val.y = fmaxf(val.y * 0.25f, 0.f);
        val.z = fmaxf(val.z * 0.25f, 0.f);
        val.w = fmaxf(val.w * 0.25f, 0.f);
        int d0 = (lane & 7) * 4;
        float l0 = val.x * Wout[(d0 + 0) * 2 + 0] + val.y * Wout[(d0 + 1) * 2 + 0]
                 + val.z * Wout[(d0 + 2) * 2 + 0] + val.w * Wout[(d0 + 3) * 2 + 0];
        float l1 = val.x * Wout[(d0 + 0) * 2 + 1] + val.y * Wout[(d0 + 1) * 2 + 1]
                 + val.z * Wout[(d0 + 2) * 2 + 1] + val.w * Wout[(d0 + 3) * 2 + 1];
        #pragma unroll
        for (int off = 4; off >= 1; off >>= 1) {
            l0 += __shfl_xor_sync(0xffffffffu, l0, off, 8);
            l1 += __shfl_xor_sync(0xffffffffu, l1, off, 8);
        }
        if (lane == 0) {
            l0 += bout[0];
            l1 += bout[1];
            float m = fmaxf(l0, l1);
            float e0 = __expf(l0 - m), e1 = __expf(l1 - m);
            float s = e0 + e1;
            outp[n * 2 + 0] = e0 / s;
            outp[n * 2 + 1] = e1 / s;
        }
    }
}

// ---------------- launch (serial schedule) ----------------
extern "C" void kernel_launch(void* const* d_in, const int* in_sizes, int n_in,
                              void* d_out, int out_size) {
    const float* in_feat = (const float*)d_in[0];
    const float* W1   = (const float*)d_in[1];
    const float* al1  = (const float*)d_in[2];
    const float* ar1  = (const float*)d_in[3];
    const float* b1   = (const float*)d_in[4];
    const float* W2   = (const float*)d_in[5];
    const float* al2  = (const float*)d_in[6];
    const float* ar2  = (const float*)d_in[7];
    const float* b2   = (const float*)d_in[8];
    const float* Wout = (const float*)d_in[9];
    const float* bout = (const float*)d_in[10];
    const int*   src  = (const int*)d_in[11];
    const int*   dst  = (const int*)d_in[12];
    float* out = (float*)d_out;

    cudaFuncSetAttribute(k_gemm, cudaFuncAttributeMaxDynamicSharedMemorySize, GEMM_SMEM);
    cudaFuncSetAttribute(k_gemm, cudaFuncAttributePreferredSharedMemoryCarveout, 100);
    cudaFuncSetAttribute(k_scan, cudaFuncAttributeMaxDynamicSharedMemorySize, NNODES * 4);

    __half* feat16_ptr = nullptr;
    cudaGetSymbolAddress((void**)&feat16_ptr, g_feat16);
    __half* h1_ptr = nullptr;
    cudaGetSymbolAddress((void**)&h1_ptr, g_h1h);
    __half* wt1_ptr = nullptr;
    cudaGetSymbolAddress((void**)&wt1_ptr, g_wt1);
    __half* wt2_ptr = nullptr;
    cudaGetSymbolAddress((void**)&wt2_ptr, g_wt2);
    int* ctr_ptr = nullptr;
    cudaGetSymbolAddress((void**)&ctr_ptr, g_tilectr);

    int agg_blocks = (NNODES * 32 + 255) / 256;
    int init_threads = FEAT4 + 32768 + NNODES + 2;
    const int GEMM_GRID = 444;   // 3 CTAs/SM x 148 SMs, persistent

    // fused init (feat->fp16 + convW + zero_deg + counters) + CSR + layer 1
    k_init<<<(init_threads + 255) / 256, 256>>>(in_feat, W1, W2);
    k_hist<<<(NEDGES + 255) / 256, 256>>>(dst);
    k_scan<<<1, 1024, NNODES * 4>>>();
    k_gemm<<<GEMM_GRID, 256, GEMM_SMEM>>>(feat16_ptr, wt1_ptr, al1, ar1, ctr_ptr);
    k_fill<<<(NEDGES + 255) / 256, 256>>>(src, dst);
    k_agg<false><<<agg_blocks, 256>>>(b1, Wout, bout, out);

    // layer 2 + head-mean + projection + softmax
    k_gemm<<<GEMM_GRID, 256, GEMM_SMEM>>>(h1_ptr, wt2_ptr, al2, ar2, ctr_ptr + 1);
    k_agg<true><<<agg_blocks, 256>>>(b2, Wout, bout, out);
}